// round 1
// baseline (speedup 1.0000x reference)
#include <cuda_runtime.h>
#include <math.h>

#define Bn 4
#define Dn 64
#define Hn 64
#define Wn 64
#define CHn 150
#define PLANE (Hn*Wn)          // 4096
#define VOL   (Dn*Hn*Wn)       // 262144
#define VOX   (Bn*VOL)         // 1048576

// Scratch (allocation-free rule: __device__ globals)
__device__ float g_p[VOX];
__device__ float g_c[VOX];   // r * (1 - p)
__device__ float g_v[VOX];   // ping-pong buffer

// ---------------------------------------------------------------------------
// Kernel 1: compute p = sigmoid(sum_c pw[c]*relu(conv3x3x3_c(x)+b[c]))
//           also writes c = r*(1-p) and initializes vout = r
// Block: 256 threads = 16 w-threads (4 voxels each) x 16 h-threads
// Tile per block: 64w x 16h x 4d.  Grid: (D/4, H/16, B) = (16,4,4)
// ---------------------------------------------------------------------------
#define DCH 4
#define HT  16
#define XROW 68          // padded row (66 used) -> 16B-aligned rows
#define XHL 18
#define XDL 6

__global__ __launch_bounds__(256) void compute_p_kernel(
    const float* __restrict__ image, const float* __restrict__ hw,
    const float* __restrict__ hb,    const float* __restrict__ pw,
    float* __restrict__ vout)
{
    __shared__ float xs[XDL * XHL * XROW];   // 7344 floats = 29376 B
    __shared__ float ws[CHn * 28];           // weights padded 27->28 (16800 B)
    __shared__ float bs[CHn];
    __shared__ float ps[CHn];

    const int tid = threadIdx.x;

    // load weights (padded rows for float4 access)
    for (int i = tid; i < CHn * 27; i += 256)
        ws[(i / 27) * 28 + (i % 27)] = hw[i];
    for (int i = tid; i < CHn; i += 256) { bs[i] = hb[i]; ps[i] = pw[i]; }

    const int d0 = blockIdx.x * DCH;
    const int h0 = blockIdx.y * HT;
    const int b  = blockIdx.z;
    const float* xg = image + (size_t)b * 2 * VOL;   // channel 0 (x)
    const float* rg = xg + VOL;                      // channel 1 (r)

    // load x tile with halo (zero padded outside volume)
    for (int i = tid; i < XDL * XHL * 66; i += 256) {
        int wl = i % 66; int rest = i / 66;
        int hl = rest % XHL; int dl = rest / XHL;
        int gw = wl - 1, gh = h0 + hl - 1, gd = d0 + dl - 1;
        float v = 0.0f;
        if (gw >= 0 && gw < Wn && gh >= 0 && gh < Hn && gd >= 0 && gd < Dn)
            v = xg[((size_t)gd * Hn + gh) * Wn + gw];
        xs[(dl * XHL + hl) * XROW + wl] = v;
    }
    __syncthreads();

    const int wt = tid & 15;
    const int ht = tid >> 4;
    const int w0 = wt * 4;

    for (int dl = 0; dl < DCH; dl++) {
        // gather 3x3x6 input neighborhood into registers
        float xr[3][3][6];
        #pragma unroll
        for (int dz = 0; dz < 3; dz++)
            #pragma unroll
            for (int hy = 0; hy < 3; hy++) {
                const float* base = &xs[((dl + dz) * XHL + (ht + hy)) * XROW + w0];
                float4 a  = *(const float4*)base;
                float2 b2 = *(const float2*)(base + 4);
                xr[dz][hy][0] = a.x;  xr[dz][hy][1] = a.y;
                xr[dz][hy][2] = a.z;  xr[dz][hy][3] = a.w;
                xr[dz][hy][4] = b2.x; xr[dz][hy][5] = b2.y;
            }

        float z0 = 0.f, z1 = 0.f, z2 = 0.f, z3 = 0.f;

        #pragma unroll 1
        for (int c = 0; c < CHn; c++) {
            const float4* wp = (const float4*)&ws[c * 28];
            float wv[28];
            #pragma unroll
            for (int q = 0; q < 7; q++) ((float4*)wv)[q] = wp[q];

            const float bias = bs[c];
            float a0 = bias, a1 = bias, a2 = bias, a3 = bias;
            #pragma unroll
            for (int dz = 0; dz < 3; dz++)
                #pragma unroll
                for (int hy = 0; hy < 3; hy++)
                    #pragma unroll
                    for (int kx = 0; kx < 3; kx++) {
                        const float wvt = wv[dz * 9 + hy * 3 + kx];
                        a0 = fmaf(wvt, xr[dz][hy][kx + 0], a0);
                        a1 = fmaf(wvt, xr[dz][hy][kx + 1], a1);
                        a2 = fmaf(wvt, xr[dz][hy][kx + 2], a2);
                        a3 = fmaf(wvt, xr[dz][hy][kx + 3], a3);
                    }
            const float pc = ps[c];
            z0 = fmaf(pc, fmaxf(a0, 0.f), z0);
            z1 = fmaf(pc, fmaxf(a1, 0.f), z1);
            z2 = fmaf(pc, fmaxf(a2, 0.f), z2);
            z3 = fmaf(pc, fmaxf(a3, 0.f), z3);
        }

        const int gd = d0 + dl, gh = h0 + ht;
        const size_t o = ((size_t)b * Dn + gd) * PLANE + gh * Wn + w0;
        const float4 r4 = *(const float4*)&rg[((size_t)gd * Hn + gh) * Wn + w0];

        float p0 = 1.f / (1.f + __expf(-z0));
        float p1 = 1.f / (1.f + __expf(-z1));
        float p2 = 1.f / (1.f + __expf(-z2));
        float p3 = 1.f / (1.f + __expf(-z3));

        *(float4*)&g_p[o]  = make_float4(p0, p1, p2, p3);
        *(float4*)&g_c[o]  = make_float4(r4.x * (1.f - p0), r4.y * (1.f - p1),
                                         r4.z * (1.f - p2), r4.w * (1.f - p3));
        *(float4*)&vout[o] = r4;   // v initialized to r
    }
}

// ---------------------------------------------------------------------------
// Kernel 2: one propagation iteration.
// v_new = max(v, c + p * maxpool3(v)),  maxpool separable z -> h -> w in SMEM.
// One block per (b,d) plane.  Block 256 threads; thread = (w, 16 h-rows).
// ---------------------------------------------------------------------------
__global__ __launch_bounds__(256) void iter_kernel(
    const float* __restrict__ vin, float* __restrict__ vout,
    const int* __restrict__ kptr, int it)
{
    __shared__ float vz[PLANE];
    __shared__ float vzh[PLANE];

    const int bd = blockIdx.x;        // b*64 + d
    const int d  = bd & 63;
    const float* vb = vin + (size_t)bd * PLANE;
    const int tid = threadIdx.x;
    const int w  = tid & 63;
    const int hq = tid >> 6;          // 0..3, each covers 16 h rows
    const bool skip = (it >= *kptr);

    float vcen[16];
    #pragma unroll
    for (int rr = 0; rr < 16; rr++) {
        const int h = hq * 16 + rr;
        const int off = h * 64 + w;
        const float cv = vb[off];
        vcen[rr] = cv;
        float m = cv;
        if (d > 0)  m = fmaxf(m, vb[off - PLANE]);
        if (d < 63) m = fmaxf(m, vb[off + PLANE]);
        vz[off] = m;
    }
    __syncthreads();

    #pragma unroll
    for (int rr = 0; rr < 16; rr++) {
        const int h = hq * 16 + rr;
        const int off = h * 64 + w;
        float m = vz[off];
        if (h > 0)  m = fmaxf(m, vz[off - 64]);
        if (h < 63) m = fmaxf(m, vz[off + 64]);
        vzh[off] = m;
    }
    __syncthreads();

    float* vo = vout + (size_t)bd * PLANE;
    const float* pp = g_p + (size_t)bd * PLANE;
    const float* cc = g_c + (size_t)bd * PLANE;
    #pragma unroll
    for (int rr = 0; rr < 16; rr++) {
        const int h = hq * 16 + rr;
        const int off = h * 64 + w;
        float m = vzh[off];
        if (w > 0)  m = fmaxf(m, vzh[off - 1]);
        if (w < 63) m = fmaxf(m, vzh[off + 1]);
        const float nv = fmaxf(vcen[rr], fmaf(pp[off], m, cc[off]));
        vo[off] = skip ? vcen[rr] : nv;
    }
}

// ---------------------------------------------------------------------------
extern "C" void kernel_launch(void* const* d_in, const int* in_sizes, int n_in,
                              void* d_out, int out_size)
{
    const float* image = (const float*)d_in[0];
    const float* hw    = (const float*)d_in[1];
    const float* hb    = (const float*)d_in[2];
    const float* pw    = (const float*)d_in[3];
    const int*   kptr  = (const int*)d_in[4];
    float* out = (float*)d_out;

    void* pv = nullptr;
    cudaGetSymbolAddress(&pv, g_v);
    float* vbuf = (float*)pv;

    compute_p_kernel<<<dim3(16, 4, 4), 256>>>(image, hw, hb, pw, out);

    const float* src = out;
    float* dst = vbuf;
    for (int i = 0; i < 30; i++) {
        iter_kernel<<<Bn * Dn, 256>>>(src, dst, kptr, i);
        float* t = dst; dst = (float*)src; src = t;
    }
    // i=29 (odd) wrote to d_out: final result lands in out.
}

// round 2
// speedup vs baseline: 1.7353x; 1.7353x over previous
#include <cuda_runtime.h>
#include <math.h>

#define Bn 4
#define Dn 64
#define Hn 64
#define Wn 64
#define CHn 150
#define PLANE 4096
#define VOL   262144
#define VOX   1048576

typedef unsigned long long ull;

// Scratch (allocation-free rule: __device__ globals)
__device__ float g_p[VOX];
__device__ float g_c[VOX];   // r * (1 - p)
__device__ float g_v[VOX];   // ping-pong buffer

// ---------------- packed f32x2 helpers (sm_103a) ----------------
__device__ __forceinline__ ull pk2(float a, float b) {
    ull r; asm("mov.b64 %0, {%1, %2};" : "=l"(r) : "f"(a), "f"(b)); return r;
}
__device__ __forceinline__ void upk2(ull v, float& a, float& b) {
    asm("mov.b64 {%0, %1}, %2;" : "=f"(a), "=f"(b) : "l"(v));
}
__device__ __forceinline__ ull fma2(ull a, ull b, ull c) {
    ull d; asm("fma.rn.f32x2 %0, %1, %2, %3;" : "=l"(d) : "l"(a), "l"(b), "l"(c));
    return d;
}
__device__ __forceinline__ float4 max4(float4 a, float4 b) {
    return make_float4(fmaxf(a.x, b.x), fmaxf(a.y, b.y),
                       fmaxf(a.z, b.z), fmaxf(a.w, b.w));
}

// ---------------------------------------------------------------------------
// Kernel 1: p = sigmoid(sum_c pw[c]*relu(conv3x3x3_c(x)+b[c]))
//           also writes c = r*(1-p) and initializes vout = r
// FFMA2 path: weights/bias/pw duplicated in SMEM as float2; x window packed
// into shifted f32x2 pairs once per d-slice and reused for all 150 channels.
// Block 256 thr = 16w-thr (4 voxels) x 16h.  Tile 64w x 16h x 4d. Grid (16,4,4)
// ---------------------------------------------------------------------------
#define DCH 4
#define HT  16
#define XROW 68
#define XHL 18
#define XDL 6

__global__ __launch_bounds__(256) void compute_p_kernel(
    const float* __restrict__ image, const float* __restrict__ hw,
    const float* __restrict__ hb,    const float* __restrict__ pw,
    float* __restrict__ vout)
{
    __shared__ float  xs[XDL * XHL * XROW];   // 29376 B
    __shared__ float2 ws2[CHn * 28];          // duplicated weights, 33600 B
    __shared__ float2 bs2[CHn];
    __shared__ float2 ps2[CHn];

    const int tid = threadIdx.x;

    for (int i = tid; i < CHn * 27; i += 256) {
        float w = hw[i];
        ws2[(i / 27) * 28 + (i % 27)] = make_float2(w, w);
    }
    for (int i = tid; i < CHn; i += 256) {
        float b = hb[i], p = pw[i];
        bs2[i] = make_float2(b, b);
        ps2[i] = make_float2(p, p);
    }

    const int d0 = blockIdx.x * DCH;
    const int h0 = blockIdx.y * HT;
    const int b  = blockIdx.z;
    const float* xg = image + (size_t)b * 2 * VOL;   // channel 0 (x)
    const float* rg = xg + VOL;                      // channel 1 (r)

    for (int i = tid; i < XDL * XHL * 66; i += 256) {
        int wl = i % 66; int rest = i / 66;
        int hl = rest % XHL; int dl = rest / XHL;
        int gw = wl - 1, gh = h0 + hl - 1, gd = d0 + dl - 1;
        float v = 0.0f;
        if (gw >= 0 && gw < Wn && gh >= 0 && gh < Hn && gd >= 0 && gd < Dn)
            v = xg[((size_t)gd * Hn + gh) * Wn + gw];
        xs[(dl * XHL + hl) * XROW + wl] = v;
    }
    __syncthreads();

    const int wt = tid & 15;
    const int ht = tid >> 4;
    const int w0 = wt * 4;

    for (int dl = 0; dl < DCH; dl++) {
        // Pack shifted pairs: P[row][j] = (x[w0-1+j], x[w0+j]), j=0..4
        ull P[9][5];
        #pragma unroll
        for (int r9 = 0; r9 < 9; r9++) {
            const int dz = r9 / 3, hy = r9 % 3;
            const float* base = &xs[((dl + dz) * XHL + (ht + hy)) * XROW + w0];
            float4 a  = *(const float4*)base;
            float2 b2 = *(const float2*)(base + 4);
            P[r9][0] = pk2(a.x, a.y);
            P[r9][1] = pk2(a.y, a.z);
            P[r9][2] = pk2(a.z, a.w);
            P[r9][3] = pk2(a.w, b2.x);
            P[r9][4] = pk2(b2.x, b2.y);
        }

        ull z01 = 0ull, z23 = 0ull;   // (+0.f, +0.f)

        #pragma unroll 1
        for (int c = 0; c < CHn; c++) {
            const ull* wp = (const ull*)&ws2[c * 28];
            const ull  bv = *(const ull*)&bs2[c];
            ull a01 = bv, a23 = bv;
            #pragma unroll
            for (int t = 0; t < 27; t++) {
                const ull w2 = wp[t];
                const int r9 = t / 3, kx = t % 3;
                a01 = fma2(w2, P[r9][kx],     a01);
                a23 = fma2(w2, P[r9][kx + 2], a23);
            }
            float a0, a1, a2, a3;
            upk2(a01, a0, a1); upk2(a23, a2, a3);
            a0 = fmaxf(a0, 0.f); a1 = fmaxf(a1, 0.f);
            a2 = fmaxf(a2, 0.f); a3 = fmaxf(a3, 0.f);
            const ull pv = *(const ull*)&ps2[c];
            z01 = fma2(pv, pk2(a0, a1), z01);
            z23 = fma2(pv, pk2(a2, a3), z23);
        }

        float z0, z1, z2, z3;
        upk2(z01, z0, z1); upk2(z23, z2, z3);

        const int gd = d0 + dl, gh = h0 + ht;
        const size_t o = ((size_t)b * Dn + gd) * PLANE + gh * Wn + w0;
        const float4 r4 = *(const float4*)&rg[((size_t)gd * Hn + gh) * Wn + w0];

        const float p0 = 1.f / (1.f + __expf(-z0));
        const float p1 = 1.f / (1.f + __expf(-z1));
        const float p2 = 1.f / (1.f + __expf(-z2));
        const float p3 = 1.f / (1.f + __expf(-z3));

        *(float4*)&g_p[o]  = make_float4(p0, p1, p2, p3);
        *(float4*)&g_c[o]  = make_float4(r4.x * (1.f - p0), r4.y * (1.f - p1),
                                         r4.z * (1.f - p2), r4.w * (1.f - p3));
        *(float4*)&vout[o] = r4;
    }
}

// ---------------------------------------------------------------------------
// Kernel 2: one propagation iteration (sliced planes, 1024 blocks).
// v_new = max(v, c + p*maxpool3(v)).  d-max -> SMEM, h-max + w-max fused via
// warp shuffles (single __syncthreads).  All global traffic float4.
// Block = 256 thr, slice = 16 h-rows x 64 w of one (b,d) plane.
// ---------------------------------------------------------------------------
__global__ __launch_bounds__(256) void iter_kernel(
    const float4* __restrict__ vin, float4* __restrict__ vout,
    const int* __restrict__ kptr, int it)
{
    __shared__ float4 vz[18 * 16];    // d-max, rows h0-1 .. h0+16 (clamped)

    const int blk = blockIdx.x;
    const int bd  = blk >> 2;         // b*64 + d
    const int hs  = blk & 3;
    const int h0  = hs * 16;
    const int d   = bd & 63;
    const int tid = threadIdx.x;
    const bool skip = (it >= *kptr);

    const size_t base = (size_t)bd * 1024;      // plane base in float4 units
    const long long dm = (d > 0)  ? -1024 : 0;
    const long long dp = (d < 63) ?  1024 : 0;

    // Stage 1: d-max for 18 rows x 16 float4
    for (int i = tid; i < 18 * 16; i += 256) {
        const int row = i >> 4, c4 = i & 15;
        int gh = h0 + row - 1;
        gh = max(0, min(63, gh));
        const size_t off = base + gh * 16 + c4;
        float4 m = vin[off];
        m = max4(m, vin[off + dm]);
        m = max4(m, vin[off + dp]);
        vz[row * 16 + c4] = m;
    }
    __syncthreads();

    // Stage 2: h-max + w-max + update (one task per thread; 16 rows x 16 c4)
    {
        const int h  = tid >> 4;      // 0..15
        const int c4 = tid & 15;      // 0..15

        float4 hm = max4(max4(vz[h * 16 + c4], vz[(h + 1) * 16 + c4]),
                         vz[(h + 2) * 16 + c4]);

        float lf = __shfl_up_sync(0xffffffffu, hm.w, 1);
        float rt = __shfl_down_sync(0xffffffffu, hm.x, 1);
        if (c4 == 0)  lf = hm.x;      // w==0 edge (also fixes row crossing)
        if (c4 == 15) rt = hm.w;      // w==63 edge

        float4 m;
        m.x = fmaxf(lf,   fmaxf(hm.x, hm.y));
        m.y = fmaxf(hm.x, fmaxf(hm.y, hm.z));
        m.z = fmaxf(hm.y, fmaxf(hm.z, hm.w));
        m.w = fmaxf(hm.z, fmaxf(hm.w, rt));

        const size_t off = base + (h0 + h) * 16 + c4;
        const float4 cen = vin[off];
        const float4 pp  = ((const float4*)g_p)[off];
        const float4 cc  = ((const float4*)g_c)[off];

        float4 nv;
        nv.x = fmaxf(cen.x, fmaf(pp.x, m.x, cc.x));
        nv.y = fmaxf(cen.y, fmaf(pp.y, m.y, cc.y));
        nv.z = fmaxf(cen.z, fmaf(pp.z, m.z, cc.z));
        nv.w = fmaxf(cen.w, fmaf(pp.w, m.w, cc.w));

        vout[off] = skip ? cen : nv;
    }
}

// ---------------------------------------------------------------------------
extern "C" void kernel_launch(void* const* d_in, const int* in_sizes, int n_in,
                              void* d_out, int out_size)
{
    const float* image = (const float*)d_in[0];
    const float* hw    = (const float*)d_in[1];
    const float* hb    = (const float*)d_in[2];
    const float* pw    = (const float*)d_in[3];
    const int*   kptr  = (const int*)d_in[4];
    float* out = (float*)d_out;

    void* pv = nullptr;
    cudaGetSymbolAddress(&pv, g_v);
    float* vbuf = (float*)pv;

    compute_p_kernel<<<dim3(16, 4, 4), 256>>>(image, hw, hb, pw, out);

    const float* src = out;
    float* dst = vbuf;
    for (int i = 0; i < 30; i++) {
        iter_kernel<<<Bn * Dn * 4, 256>>>((const float4*)src, (float4*)dst, kptr, i);
        float* t = dst; dst = (float*)src; src = t;
    }
    // 30 iterations (even): final write lands in d_out.
}